// round 15
// baseline (speedup 1.0000x reference)
#include <cuda_runtime.h>
#include <cuda_bf16.h>
#include <math.h>
#include <stdint.h>

constexpr int NS = 1024, NB = 64, NE = 512, NH = 512, NH3 = 1536, NV = 32000;
constexpr int NCG = 32, NGB = 32, JS = 16, NROW = 48, REC_THREADS = 512;

// gru_rec smem byte offsets (from 1024-aligned base)
constexpr int OFF_A   = 0;        // A tile: 64 x 512 bf16 (row stride 1024B)
constexpr int OFF_WHI = 65536;
constexpr int OFF_WLO = 114688;
constexpr int OFF_P   = 163840;   // partials [2][96][50] f32
constexpr int OFF_HPS = 202240;   // hp [32][52] f32 (6656B)
constexpr int OFF_SST = 208896;   // reduced stats [192] f32
constexpr int REC_SMEM_BYTES = 208896 + 768 + 1024;

// hgemm smem: 4 tiles of [128 rows][64 k] bf16 (16KB each)
constexpr int HG_SMEM = 65536;

// ---------------- warp mma / ldmatrix (base PTX, sm_80+) ----------------
__device__ __forceinline__ uint32_t smem_u32(const void* p) {
    uint32_t a;
    asm("{ .reg .u64 t; cvta.to.shared.u64 t, %1; cvt.u32.u64 %0, t; }" : "=r"(a) : "l"(p));
    return a;
}
__device__ __forceinline__ void ldsm4(uint32_t* r, uint32_t addr) {
    asm volatile("ldmatrix.sync.aligned.m8n8.x4.shared.b16 {%0,%1,%2,%3}, [%4];"
        : "=r"(r[0]), "=r"(r[1]), "=r"(r[2]), "=r"(r[3]) : "r"(addr));
}
__device__ __forceinline__ void ldsm2(uint32_t* r, uint32_t addr) {
    asm volatile("ldmatrix.sync.aligned.m8n8.x2.shared.b16 {%0,%1}, [%2];"
        : "=r"(r[0]), "=r"(r[1]) : "r"(addr));
}
__device__ __forceinline__ void mma16816(float* d, const uint32_t* a, const uint32_t* b) {
    asm volatile("mma.sync.aligned.m16n8k16.row.col.f32.bf16.bf16.f32 "
        "{%0,%1,%2,%3}, {%4,%5,%6,%7}, {%8,%9}, {%0,%1,%2,%3};"
        : "+f"(d[0]), "+f"(d[1]), "+f"(d[2]), "+f"(d[3])
        : "r"(a[0]), "r"(a[1]), "r"(a[2]), "r"(a[3]), "r"(b[0]), "r"(b[1]));
}
// swizzled byte offset, row stride 1024B (gru tiles), k4 = 8B unit
__device__ __forceinline__ uint32_t tile_off(int row, int k4) {
    return (uint32_t)(row * 1024 + ((k4 * 8) ^ ((row & 7) << 4)));
}
__device__ __forceinline__ void bsplit(float4 v, uint2& hi, uint2& lo) {
    __nv_bfloat16 a = __float2bfloat16_rn(v.x), b = __float2bfloat16_rn(v.y),
                  c = __float2bfloat16_rn(v.z), d = __float2bfloat16_rn(v.w);
    __nv_bfloat162 h0 = __halves2bfloat162(a, b), h1 = __halves2bfloat162(c, d);
    hi.x = *(uint32_t*)&h0; hi.y = *(uint32_t*)&h1;
    __nv_bfloat162 l0 = __floats2bfloat162_rn(v.x - __bfloat162float(a), v.y - __bfloat162float(b));
    __nv_bfloat162 l1 = __floats2bfloat162_rn(v.z - __bfloat162float(c), v.w - __bfloat162float(d));
    lo.x = *(uint32_t*)&l0; lo.y = *(uint32_t*)&l1;
}

// ---------------- device scratch ----------------
__device__ float g_Wp0[(size_t)NV * NH3];
__device__ float g_Wp1[(size_t)NV * NH3];
__device__ float g_gru[(size_t)NS * NB * 2 * NH];
__device__ __nv_bfloat16 g_hbf[4][2][NGB * NH];   // [group][hi/lo][b*512+k]
__device__ float g_pstT[4][192][NCG];             // LN stat partials, stat-major
__device__ unsigned g_flagS[4][NCG][32];          // 128B-padded per-CTA flags
__device__ unsigned g_flagH[4][NCG][32];

// flag barrier: arrive = own-flag release store; wait = warp0 parallel poll
__device__ __forceinline__ void fbar_arrive(unsigned* flags, int cid, unsigned val) {
    __syncthreads();
    if (threadIdx.x == 0)
        asm volatile("st.release.gpu.global.u32 [%0], %1;"
                     :: "l"(flags + cid * 32), "r"(val) : "memory");
}
__device__ __forceinline__ void fbar_wait(const unsigned* flags, unsigned val) {
    if (threadIdx.x < 32) {
        const unsigned* p = flags + threadIdx.x * 32;
        unsigned v;
        do {
            asm volatile("ld.acquire.gpu.global.u32 %0, [%1];" : "=r"(v) : "l"(p) : "memory");
        } while (__any_sync(0xffffffffu, v < val));
    }
    __syncthreads();
}

// ----------------------------------------------------------------------------
// hgemm_nt (UNCHANGED): bf16-split mma GEMM.
// ----------------------------------------------------------------------------
template <int EPI>
__global__ void __launch_bounds__(256, 2) hgemm_nt(
    const float* __restrict__ A, const float* __restrict__ Bw,
    float* __restrict__ C, int M, int N, int K, const float* __restrict__ bias)
{
    extern __shared__ __align__(1024) char hsm[];
    uint32_t sb = smem_u32(hsm);
    uint32_t sAhi = sb, sAlo = sb + 16384, sBhi = sb + 32768, sBlo = sb + 49152;

    int tid = threadIdx.x, lane = tid & 31, wid = tid >> 5;
    int wm = wid & 3, wn = wid >> 2;
    const float* Ab = A + (size_t)blockIdx.y * 128 * K;
    const float* Bb = Bw + (size_t)blockIdx.x * 128 * K;

    float acc[2][8][4];
#pragma unroll
    for (int mt = 0; mt < 2; mt++)
#pragma unroll
        for (int nt = 0; nt < 8; nt++)
#pragma unroll
            for (int q = 0; q < 4; q++) acc[mt][nt][q] = 0.f;

    int aRowL = (lane & 7) + ((lane >> 3) & 1) * 8;
    int aK8 = (lane >> 4);
    int bRowL = ((lane >> 4) & 1) * 8 + (lane & 7);
    int bK8 = (lane >> 3) & 1;
    int rsub = tid >> 4, c4 = tid & 15;

    for (int kc = 0; kc < K; kc += 64) {
#pragma unroll
        for (int i = 0; i < 8; i++) {
            int row = rsub + i * 16;
            uint32_t off = (uint32_t)(row * 128 + ((c4 * 8) ^ ((row & 7) << 4)));
            float4 va = *(const float4*)(Ab + (size_t)row * K + kc + c4 * 4);
            uint2 hi, lo; bsplit(va, hi, lo);
            *(uint2*)(hsm + (sAhi - sb) + off) = hi;
            *(uint2*)(hsm + (sAlo - sb) + off) = lo;
            float4 vb = *(const float4*)(Bb + (size_t)row * K + kc + c4 * 4);
            bsplit(vb, hi, lo);
            *(uint2*)(hsm + (sBhi - sb) + off) = hi;
            *(uint2*)(hsm + (sBlo - sb) + off) = lo;
        }
        __syncthreads();
#pragma unroll
        for (int k16 = 0; k16 < 4; k16++) {
            int ku = k16 * 2;
            uint32_t ah[2][4], al[2][4];
#pragma unroll
            for (int mt = 0; mt < 2; mt++) {
                int row = wm * 32 + mt * 16 + aRowL;
                uint32_t off = (uint32_t)(row * 128 + (((ku + aK8) * 16) ^ ((row & 7) << 4)));
                ldsm4(ah[mt], sAhi + off);
                ldsm4(al[mt], sAlo + off);
            }
#pragma unroll
            for (int ntp = 0; ntp < 4; ntp++) {
                int row = wn * 64 + ntp * 16 + bRowL;
                uint32_t off = (uint32_t)(row * 128 + (((ku + bK8) * 16) ^ ((row & 7) << 4)));
                uint32_t bh[4], bl[4];
                ldsm4(bh, sBhi + off);
                ldsm4(bl, sBlo + off);
#pragma unroll
                for (int h = 0; h < 2; h++) {
                    int nt = ntp * 2 + h;
#pragma unroll
                    for (int mt = 0; mt < 2; mt++) {
                        mma16816(acc[mt][nt], ah[mt], bh + h * 2);
                        mma16816(acc[mt][nt], al[mt], bh + h * 2);
                        mma16816(acc[mt][nt], ah[mt], bl + h * 2);
                    }
                }
            }
        }
        __syncthreads();
    }

    int r0 = lane >> 2, c0 = (lane & 3) * 2;
#pragma unroll
    for (int mt = 0; mt < 2; mt++)
#pragma unroll
        for (int nt = 0; nt < 8; nt++) {
            int m = blockIdx.y * 128 + wm * 32 + mt * 16 + r0;
            int n = blockIdx.x * 128 + wn * 64 + nt * 8 + c0;
            float2 v0 = make_float2(acc[mt][nt][0], acc[mt][nt][1]);
            float2 v1 = make_float2(acc[mt][nt][2], acc[mt][nt][3]);
            if (EPI) {
                float b0 = bias[n], b1 = bias[n + 1];
                v0.x = tanhf(v0.x + b0); v0.y = tanhf(v0.y + b1);
                v1.x = tanhf(v1.x + b0); v1.y = tanhf(v1.y + b1);
            }
            *(float2*)(C + (size_t)m * N + n) = v0;
            *(float2*)(C + (size_t)(m + 8) * N + n) = v1;
        }
}

// ---------------- LN over vocab table + init ----------------
__global__ void ln_k(const float* __restrict__ gA, const float* __restrict__ beA,
                     const float* __restrict__ bA, const float* __restrict__ gB,
                     const float* __restrict__ beB, const float* __restrict__ bB)
{
    int row = blockIdx.x, tid = threadIdx.x;
    if (row < 512) {
        ((float*)g_hbf)[row * 128 + tid] = 0.f;
    } else if (row == 512) {
        // zero barrier flags (4*32*32 = 4096 uints each)
        for (int q = 0; q < 32; q++) {
            ((unsigned*)g_flagS)[q * 128 + tid] = 0u;
            ((unsigned*)g_flagH)[q * 128 + tid] = 0u;
        }
    }
    int dir = row >= NV * 3;
    int rem = dir ? row - NV * 3 : row;
    int tok = rem / 3, gate = rem - tok * 3;
    float* p = (dir ? g_Wp1 : g_Wp0) + (size_t)tok * NH3 + gate * NH;
    const float* gg = (dir ? gB : gA) + gate * NH;
    const float* be = (dir ? beB : beA) + gate * NH;
    const float* bi = (dir ? bB : bA) + gate * NH;
    float4 v = ((float4*)p)[tid];
    if (tok == 0) { v.x = 0.f; v.y = 0.f; v.z = 0.f; v.w = 0.f; }
    float sum = v.x + v.y + v.z + v.w;
    float sq = v.x * v.x + v.y * v.y + v.z * v.z + v.w * v.w;
#pragma unroll
    for (int o = 16; o; o >>= 1) {
        sum += __shfl_xor_sync(0xffffffffu, sum, o);
        sq  += __shfl_xor_sync(0xffffffffu, sq, o);
    }
    __shared__ float ss[4], sc[4];
    int w = tid >> 5;
    if ((tid & 31) == 0) { ss[w] = sum; sc[w] = sq; }
    __syncthreads();
    sum = ss[0] + ss[1] + ss[2] + ss[3];
    sq  = sc[0] + sc[1] + sc[2] + sc[3];
    float mu = sum * (1.f / NH);
    float rs = rsqrtf(sq * (1.f / NH) - mu * mu + 1e-5f);
    int j = tid * 4;
    v.x = (v.x - mu) * rs * gg[j]     + be[j]     + bi[j];
    v.y = (v.y - mu) * rs * gg[j + 1] + be[j + 1] + bi[j + 1];
    v.z = (v.z - mu) * rs * gg[j + 2] + be[j + 2] + bi[j + 2];
    v.w = (v.w - mu) * rs * gg[j + 3] + be[j + 3] + bi[j + 3];
    ((float4*)p)[tid] = v;
}

// ----------------------------------------------------------------------------
// Persistent recurrence: flag barriers, staged-lo/hi overlap with mma,
// transposed stat partials, register-carried h, producer-side bf16 publish.
// ----------------------------------------------------------------------------
__global__ void __launch_bounds__(REC_THREADS, 1) gru_rec(
    const int* __restrict__ src,
    const float* __restrict__ Whh_f, const float* __restrict__ Whh_b,
    const float* __restrict__ ghh_f, const float* __restrict__ behh_f,
    const float* __restrict__ bhh_f, const float* __restrict__ ghh_b,
    const float* __restrict__ behh_b, const float* __restrict__ bhh_b,
    float* __restrict__ dout)
{
    extern __shared__ __align__(16) char smraw[];
    uint32_t sb0 = smem_u32(smraw);
    uint32_t sb = (sb0 + 1023) & ~1023u;
    char* basep = smraw + (sb - sb0);
    float* Pbuf = (float*)(basep + OFF_P);
    float* hpsp = (float*)(basep + OFF_HPS);
    float* sstat = (float*)(basep + OFF_SST);

    int grp = blockIdx.x >> 5, cid = blockIdx.x & 31;
    int dir = grp >> 1, bh = grp & 1;
    int tid = threadIdx.x, lane = tid & 31, wid = tid >> 5;
    int jbase = cid * JS;

    const float* Whh  = dir ? Whh_b  : Whh_f;
    const float* ghh  = dir ? ghh_b  : ghh_f;
    const float* behh = dir ? behh_b : behh_f;
    const float* bhh  = dir ? bhh_b  : bhh_f;
    const float* Wp   = dir ? g_Wp1  : g_Wp0;
    const uint4* hbhi = (const uint4*)g_hbf[grp][0];
    const uint4* hblo = (const uint4*)g_hbf[grp][1];
    unsigned* flS = &g_flagS[grp][0][0];
    unsigned* flH = &g_flagH[grp][0][0];

    // one-time: W -> bf16 hi/lo swizzled tiles
    for (int idx = tid; idx < NROW * 128; idx += REC_THREADS) {
        int r = idx >> 7, k4 = idx & 127;
        int grow = (r >> 4) * NH + jbase + (r & 15);
        float4 v = *(const float4*)(Whh + (size_t)grow * NH + k4 * 4);
        uint2 hi, lo; bsplit(v, hi, lo);
        uint32_t off = tile_off(r, k4);
        *(uint2*)(basep + OFF_WHI + off) = hi;
        *(uint2*)(basep + OFF_WLO + off) = lo;
    }

    int kh = wid / 6;
    int sp = wid % 6;
    bool t3 = sp >= 4;
    int mrowbase = t3 ? 0 : (sp >> 1) * 32;
    int ntb = t3 ? (sp - 4) * 24 : (sp & 1) * 24;
    int prow = t3 ? 64 : (sp >> 1) * 32;
    int khb = kh * 256;
    int aRow0 = mrowbase + (lane & 7) + ((lane >> 3) & 1) * 8;
    int aKoff = (lane >> 4) * 8;
    uint32_t swzl = (uint32_t)((lane & 7) << 4);
    uint32_t aBase0 = sb + OFF_A + aRow0 * 1024;
    uint32_t wTile = sb + (t3 ? OFF_WLO : OFF_WHI);
    int bKoff = ((lane >> 3) & 1) * 8;
    uint32_t bBase[3];
#pragma unroll
    for (int nt = 0; nt < 3; nt++)
        bBase[nt] = wTile + (ntb + nt * 8 + (lane & 7)) * 1024;

    int pb = tid >> 4, jl = tid & 15;
    float cg[3], cbe[3], cbb[3];
#pragma unroll
    for (int g = 0; g < 3; g++) {
        int j = g * NH + jbase + jl;
        cg[g] = ghh[j]; cbe[g] = behh[j]; cbb[g] = bhh[j];
    }
    float xv[3];
    {
        int s0 = dir ? (NS - 1) : 0;
        int tok = __ldg(src + s0 * NB + bh * NGB + pb);
        const float* xrow = Wp + (size_t)tok * NH3;
#pragma unroll
        for (int g = 0; g < 3; g++) xv[g] = __ldg(xrow + g * NH + jbase + jl);
    }
    float hprev = 0.f;
    __syncthreads();

    for (int t = 0; t < NS; t++) {
        int s = dir ? (NS - 1 - t) : t;

        if (t > 0) fbar_wait(flH, (unsigned)t);

        // L2-prefetch x(t+1) rows
        if (t + 1 < NS && (jl & 7) == 0) {
            int sn = dir ? (NS - 2 - t) : (t + 1);
            int tokp = __ldg(src + sn * NB + bh * NGB + pb);
            const float* xrp = Wp + (size_t)tokp * NH3 + jbase + jl;
#pragma unroll
            for (int g = 0; g < 3; g++)
                asm volatile("prefetch.global.L2 [%0];" :: "l"(xrp + g * NH));
        }

        // stage LO k-half (u 0..31) by all 512 threads
#pragma unroll
        for (int i = 0; i < 4; i++) {
            int unit = tid + i * REC_THREADS;       // 0..2047
            int row = unit >> 5, u = unit & 31;
            const uint4* srcp = (row < 32) ? hbhi : hblo;
            uint4 v = srcp[(row & 31) * 64 + u];
            *(uint4*)(basep + OFF_A + row * 1024 + ((u * 16) ^ ((row & 7) << 4))) = v;
        }
        asm volatile("bar.sync 1, %0;" :: "r"(REC_THREADS) : "memory");

        // warps 8-15: stage HI k-half (u 32..63) while warps 0-5 run mma(kh=0)
        if (wid >= 8) {
            int ht = tid - 256;
#pragma unroll
            for (int i = 0; i < 8; i++) {
                int unit = ht + i * 256;            // 0..2047
                int row = unit >> 5, u = 32 + (unit & 31);
                const uint4* srcp = (row < 32) ? hbhi : hblo;
                uint4 v = srcp[(row & 31) * 64 + u];
                *(uint4*)(basep + OFF_A + row * 1024 + ((u * 16) ^ ((row & 7) << 4))) = v;
            }
        }

        if (wid < 12) {
            if (kh == 1)
                asm volatile("bar.sync 2, 320;" ::: "memory");
            float acc[2][3][4];
#pragma unroll
            for (int mt = 0; mt < 2; mt++)
#pragma unroll
                for (int nt = 0; nt < 3; nt++)
#pragma unroll
                    for (int q = 0; q < 4; q++) acc[mt][nt][q] = 0.f;
#pragma unroll 4
            for (int kc = 0; kc < 16; kc++) {
                int kb = khb + kc * 16;
                uint32_t a0[4], a1[4];
                uint32_t ad = aBase0 + ((uint32_t)((kb + aKoff) * 2) ^ swzl);
                ldsm4(a0, ad);
                ldsm4(a1, ad + 16 * 1024);
                uint32_t bf[3][2];
                uint32_t bko = (uint32_t)((kb + bKoff) * 2) ^ swzl;
#pragma unroll
                for (int nt = 0; nt < 3; nt++) ldsm2(bf[nt], bBase[nt] + bko);
#pragma unroll
                for (int nt = 0; nt < 3; nt++) {
                    mma16816(acc[0][nt], a0, bf[nt]);
                    mma16816(acc[1][nt], a1, bf[nt]);
                }
            }
            float* P = Pbuf + kh * (96 * 50);
            int r0 = lane >> 2, c0 = (lane & 3) * 2;
#pragma unroll
            for (int mt = 0; mt < 2; mt++)
#pragma unroll
                for (int nt = 0; nt < 3; nt++) {
                    float* rp = P + (prow + mt * 16 + r0) * 50 + ntb + nt * 8 + c0;
                    *(float2*)rp = make_float2(acc[mt][nt][0], acc[mt][nt][1]);
                    *(float2*)(rp + 8 * 50) = make_float2(acc[mt][nt][2], acc[mt][nt][3]);
                }
        } else {
            asm volatile("bar.sync 2, 320;" ::: "memory");
        }
        __syncthreads();

#pragma unroll
        for (int i = 0; i < 3; i++) {
            int e = tid + i * REC_THREADS;
            int b = e / 48, r = e - b * 48;
            const float* P0 = Pbuf + b * 50 + r;
            const float* P1 = P0 + 96 * 50;
            float v = P0[0] + P0[32 * 50] + P0[64 * 50]
                    + P1[0] + P1[32 * 50] + P1[64 * 50];
            hpsp[b * 52 + r] = v;
        }
        __syncthreads();

        // LN partial stats -> transposed slot (stat-major; contention-free)
        if (tid < 96) {
            int g = tid >> 5, b = tid & 31;
            float sv = 0.f, sq = 0.f;
#pragma unroll
            for (int q = 0; q < 16; q++) {
                float v = hpsp[b * 52 + g * 16 + q];
                sv += v; sq += v * v;
            }
            int s0 = b * 6 + g * 2;
            g_pstT[grp][s0][cid] = sv;
            g_pstT[grp][s0 + 1][cid] = sq;
        }
        fbar_arrive(flS, cid, (unsigned)(t + 1));

        // x(t+1) loads (hit L2 thanks to prefetch)
        float xn[3];
        if (t + 1 < NS) {
            int sn = dir ? (NS - 2 - t) : (t + 1);
            int tok = __ldg(src + sn * NB + bh * NGB + pb);
            const float* xrow = Wp + (size_t)tok * NH3;
#pragma unroll
            for (int g = 0; g < 3; g++) xn[g] = __ldg(xrow + g * NH + jbase + jl);
        }

        fbar_wait(flS, (unsigned)(t + 1));

        // reduce stats across CTAs: 32 contiguous floats per stat (8x float4)
        if (tid < 192) {
            const float4* pp = (const float4*)&g_pstT[grp][tid][0];
            float4 a0 = pp[0], a1 = pp[1], a2 = pp[2], a3 = pp[3];
            float4 a4 = pp[4], a5 = pp[5], a6 = pp[6], a7 = pp[7];
            float v = a0.x + a0.y + a0.z + a0.w + a1.x + a1.y + a1.z + a1.w
                    + a2.x + a2.y + a2.z + a2.w + a3.x + a3.y + a3.z + a3.w
                    + a4.x + a4.y + a4.z + a4.w + a5.x + a5.y + a5.z + a5.w
                    + a6.x + a6.y + a6.z + a6.w + a7.x + a7.y + a7.z + a7.w;
            sstat[tid] = v;
        }
        __syncthreads();

        float hnew;
        {
            const float* st = sstat + pb * 6;
            float mu0 = st[0] * (1.f / NH);
            float rs0 = rsqrtf(st[1] * (1.f / NH) - mu0 * mu0 + 1e-5f);
            float mu1 = st[2] * (1.f / NH);
            float rs1 = rsqrtf(st[3] * (1.f / NH) - mu1 * mu1 + 1e-5f);
            float mu2 = st[4] * (1.f / NH);
            float rs2 = rsqrtf(st[5] * (1.f / NH) - mu2 * mu2 + 1e-5f);
            float hr = (hpsp[pb * 52 + jl]      - mu0) * rs0 * cg[0] + cbe[0] + cbb[0];
            float hz = (hpsp[pb * 52 + 16 + jl] - mu1) * rs1 * cg[1] + cbe[1] + cbb[1];
            float hn = (hpsp[pb * 52 + 32 + jl] - mu2) * rs2 * cg[2] + cbe[2] + cbb[2];
            float r = 1.f / (1.f + __expf(-(xv[0] + hr)));
            float z = 1.f / (1.f + __expf(-(xv[1] + hz)));
            float n = tanhf(xv[2] + r * hn);
            hnew = (1.f - z) * n + z * hprev;
            hprev = hnew;
            __nv_bfloat16 hi = __float2bfloat16_rn(hnew);
            __nv_bfloat16 lo = __float2bfloat16_rn(hnew - __bfloat162float(hi));
            g_hbf[grp][0][pb * NH + jbase + jl] = hi;
            g_hbf[grp][1][pb * NH + jbase + jl] = lo;
        }
        fbar_arrive(flH, cid, (unsigned)(t + 1));

        {
            int j = jbase + jl;
            int bglob = bh * NGB + pb;
            g_gru[((size_t)s * NB + bglob) * (2 * NH) + dir * NH + j] = hnew;
            if (t == NS - 1)
                dout[(size_t)NS * NB * NH + (size_t)dir * NB * NH + bglob * NH + j] = hnew;
        }
        xv[0] = xn[0]; xv[1] = xn[1]; xv[2] = xn[2];
    }
}

// ---------------- launch ----------------
extern "C" void kernel_launch(void* const* d_in, const int* in_sizes, int n_in,
                              void* d_out, int out_size) {
    (void)in_sizes; (void)n_in; (void)out_size;
    const int*   src    = (const int*)  d_in[0];
    const float* emb    = (const float*)d_in[1];
    const float* W_ih_f = (const float*)d_in[2];
    const float* W_hh_f = (const float*)d_in[3];
    const float* b_ih_f = (const float*)d_in[4];
    const float* bhh_f  = (const float*)d_in[5];
    const float* gih_f  = (const float*)d_in[6];
    const float* beih_f = (const float*)d_in[7];
    const float* ghh_f  = (const float*)d_in[8];
    const float* behh_f = (const float*)d_in[9];
    const float* W_ih_b = (const float*)d_in[10];
    const float* W_hh_b = (const float*)d_in[11];
    const float* b_ih_b = (const float*)d_in[12];
    const float* bhh_b  = (const float*)d_in[13];
    const float* gih_b  = (const float*)d_in[14];
    const float* beih_b = (const float*)d_in[15];
    const float* ghh_b  = (const float*)d_in[16];
    const float* behh_b = (const float*)d_in[17];
    const float* W_out  = (const float*)d_in[18];
    const float* b_out  = (const float*)d_in[19];
    float* out = (float*)d_out;

    void *pWp0, *pWp1, *pGru;
    cudaGetSymbolAddress(&pWp0, g_Wp0);
    cudaGetSymbolAddress(&pWp1, g_Wp1);
    cudaGetSymbolAddress(&pGru, g_gru);
    cudaFuncSetAttribute(gru_rec, cudaFuncAttributeMaxDynamicSharedMemorySize,
                         REC_SMEM_BYTES);
    cudaFuncSetAttribute(hgemm_nt<0>, cudaFuncAttributeMaxDynamicSharedMemorySize,
                         HG_SMEM);
    cudaFuncSetAttribute(hgemm_nt<1>, cudaFuncAttributeMaxDynamicSharedMemorySize,
                         HG_SMEM);

    hgemm_nt<0><<<dim3(NH3 / 128, NV / 128), 256, HG_SMEM>>>(
        emb, W_ih_f, (float*)pWp0, NV, NH3, NE, nullptr);
    hgemm_nt<0><<<dim3(NH3 / 128, NV / 128), 256, HG_SMEM>>>(
        emb, W_ih_b, (float*)pWp1, NV, NH3, NE, nullptr);

    ln_k<<<2 * NV * 3, 128>>>(gih_f, beih_f, b_ih_f, gih_b, beih_b, b_ih_b);

    gru_rec<<<128, REC_THREADS, REC_SMEM_BYTES>>>(
        src, W_hh_f, W_hh_b, ghh_f, behh_f, bhh_f, ghh_b, behh_b, bhh_b, out);

    hgemm_nt<1><<<dim3(NH / 128, (NS * NB) / 128), 256, HG_SMEM>>>(
        (const float*)pGru, W_out, out, NS * NB, NH, 2 * NH, b_out);
}

// round 16
// speedup vs baseline: 1.0470x; 1.0470x over previous
#include <cuda_runtime.h>
#include <cuda_bf16.h>
#include <math.h>
#include <stdint.h>

constexpr int NS = 1024, NB = 64, NE = 512, NH = 512, NH3 = 1536, NV = 32000;
constexpr int NCG = 32, NGB = 32, JS = 16, NROW = 48, REC_THREADS = 512;

// gru_rec smem byte offsets (from 1024-aligned base)
constexpr int OFF_A   = 0;        // A tile: 64 x 512 bf16 (row stride 1024B)
constexpr int OFF_WHI = 65536;
constexpr int OFF_WLO = 114688;
constexpr int OFF_P   = 163840;   // partials [2][96][50] f32
constexpr int OFF_HPS = 202240;   // hp [32][52] f32 (6656B)
constexpr int OFF_SST = 208896;   // reduced stats [192] f32
constexpr int REC_SMEM_BYTES = 208896 + 768 + 1024;

// hgemm smem: 4 tiles of [128 rows][64 k] bf16 (16KB each)
constexpr int HG_SMEM = 65536;

// ---------------- warp mma / ldmatrix (base PTX, sm_80+) ----------------
__device__ __forceinline__ uint32_t smem_u32(const void* p) {
    uint32_t a;
    asm("{ .reg .u64 t; cvta.to.shared.u64 t, %1; cvt.u32.u64 %0, t; }" : "=r"(a) : "l"(p));
    return a;
}
__device__ __forceinline__ void ldsm4(uint32_t* r, uint32_t addr) {
    asm volatile("ldmatrix.sync.aligned.m8n8.x4.shared.b16 {%0,%1,%2,%3}, [%4];"
        : "=r"(r[0]), "=r"(r[1]), "=r"(r[2]), "=r"(r[3]) : "r"(addr));
}
__device__ __forceinline__ void ldsm2(uint32_t* r, uint32_t addr) {
    asm volatile("ldmatrix.sync.aligned.m8n8.x2.shared.b16 {%0,%1}, [%2];"
        : "=r"(r[0]), "=r"(r[1]) : "r"(addr));
}
__device__ __forceinline__ void mma16816(float* d, const uint32_t* a, const uint32_t* b) {
    asm volatile("mma.sync.aligned.m16n8k16.row.col.f32.bf16.bf16.f32 "
        "{%0,%1,%2,%3}, {%4,%5,%6,%7}, {%8,%9}, {%0,%1,%2,%3};"
        : "+f"(d[0]), "+f"(d[1]), "+f"(d[2]), "+f"(d[3])
        : "r"(a[0]), "r"(a[1]), "r"(a[2]), "r"(a[3]), "r"(b[0]), "r"(b[1]));
}
// swizzled byte offset, row stride 1024B (gru tiles), k4 = 8B unit
__device__ __forceinline__ uint32_t tile_off(int row, int k4) {
    return (uint32_t)(row * 1024 + ((k4 * 8) ^ ((row & 7) << 4)));
}
__device__ __forceinline__ void bsplit(float4 v, uint2& hi, uint2& lo) {
    __nv_bfloat16 a = __float2bfloat16_rn(v.x), b = __float2bfloat16_rn(v.y),
                  c = __float2bfloat16_rn(v.z), d = __float2bfloat16_rn(v.w);
    __nv_bfloat162 h0 = __halves2bfloat162(a, b), h1 = __halves2bfloat162(c, d);
    hi.x = *(uint32_t*)&h0; hi.y = *(uint32_t*)&h1;
    __nv_bfloat162 l0 = __floats2bfloat162_rn(v.x - __bfloat162float(a), v.y - __bfloat162float(b));
    __nv_bfloat162 l1 = __floats2bfloat162_rn(v.z - __bfloat162float(c), v.w - __bfloat162float(d));
    lo.x = *(uint32_t*)&l0; lo.y = *(uint32_t*)&l1;
}

// ---------------- device scratch ----------------
__device__ float g_Wp0[(size_t)NV * NH3];
__device__ float g_Wp1[(size_t)NV * NH3];
__device__ float g_gru[(size_t)NS * NB * 2 * NH];
__device__ __nv_bfloat16 g_hbf[4][2][NGB * NH];   // [group][hi/lo][b*512+k]
__device__ float g_pst[4][NCG][192];              // per-CTA LN stat partials
__device__ unsigned g_ctrS[4];
__device__ unsigned g_ctrH[4];

__device__ __forceinline__ void bar_arrive(unsigned* c) {
    __syncthreads();
    if (threadIdx.x == 0)
        asm volatile("red.release.gpu.global.add.u32 [%0], 1;" :: "l"(c) : "memory");
}
__device__ __forceinline__ void bar_wait(unsigned* c, unsigned tgt) {
    if (threadIdx.x == 0) {
        unsigned v;
        do { asm volatile("ld.acquire.gpu.global.u32 %0, [%1];" : "=r"(v) : "l"(c) : "memory"); }
        while (v < tgt);
    }
    __syncthreads();
}

// ----------------------------------------------------------------------------
// hgemm_nt (UNCHANGED): bf16-split mma GEMM.
// ----------------------------------------------------------------------------
template <int EPI>
__global__ void __launch_bounds__(256, 2) hgemm_nt(
    const float* __restrict__ A, const float* __restrict__ Bw,
    float* __restrict__ C, int M, int N, int K, const float* __restrict__ bias)
{
    extern __shared__ __align__(1024) char hsm[];
    uint32_t sb = smem_u32(hsm);
    uint32_t sAhi = sb, sAlo = sb + 16384, sBhi = sb + 32768, sBlo = sb + 49152;

    int tid = threadIdx.x, lane = tid & 31, wid = tid >> 5;
    int wm = wid & 3, wn = wid >> 2;
    const float* Ab = A + (size_t)blockIdx.y * 128 * K;
    const float* Bb = Bw + (size_t)blockIdx.x * 128 * K;

    float acc[2][8][4];
#pragma unroll
    for (int mt = 0; mt < 2; mt++)
#pragma unroll
        for (int nt = 0; nt < 8; nt++)
#pragma unroll
            for (int q = 0; q < 4; q++) acc[mt][nt][q] = 0.f;

    int aRowL = (lane & 7) + ((lane >> 3) & 1) * 8;
    int aK8 = (lane >> 4);
    int bRowL = ((lane >> 4) & 1) * 8 + (lane & 7);
    int bK8 = (lane >> 3) & 1;
    int rsub = tid >> 4, c4 = tid & 15;

    for (int kc = 0; kc < K; kc += 64) {
#pragma unroll
        for (int i = 0; i < 8; i++) {
            int row = rsub + i * 16;
            uint32_t off = (uint32_t)(row * 128 + ((c4 * 8) ^ ((row & 7) << 4)));
            float4 va = *(const float4*)(Ab + (size_t)row * K + kc + c4 * 4);
            uint2 hi, lo; bsplit(va, hi, lo);
            *(uint2*)(hsm + (sAhi - sb) + off) = hi;
            *(uint2*)(hsm + (sAlo - sb) + off) = lo;
            float4 vb = *(const float4*)(Bb + (size_t)row * K + kc + c4 * 4);
            bsplit(vb, hi, lo);
            *(uint2*)(hsm + (sBhi - sb) + off) = hi;
            *(uint2*)(hsm + (sBlo - sb) + off) = lo;
        }
        __syncthreads();
#pragma unroll
        for (int k16 = 0; k16 < 4; k16++) {
            int ku = k16 * 2;
            uint32_t ah[2][4], al[2][4];
#pragma unroll
            for (int mt = 0; mt < 2; mt++) {
                int row = wm * 32 + mt * 16 + aRowL;
                uint32_t off = (uint32_t)(row * 128 + (((ku + aK8) * 16) ^ ((row & 7) << 4)));
                ldsm4(ah[mt], sAhi + off);
                ldsm4(al[mt], sAlo + off);
            }
#pragma unroll
            for (int ntp = 0; ntp < 4; ntp++) {
                int row = wn * 64 + ntp * 16 + bRowL;
                uint32_t off = (uint32_t)(row * 128 + (((ku + bK8) * 16) ^ ((row & 7) << 4)));
                uint32_t bh[4], bl[4];
                ldsm4(bh, sBhi + off);
                ldsm4(bl, sBlo + off);
#pragma unroll
                for (int h = 0; h < 2; h++) {
                    int nt = ntp * 2 + h;
#pragma unroll
                    for (int mt = 0; mt < 2; mt++) {
                        mma16816(acc[mt][nt], ah[mt], bh + h * 2);
                        mma16816(acc[mt][nt], al[mt], bh + h * 2);
                        mma16816(acc[mt][nt], ah[mt], bl + h * 2);
                    }
                }
            }
        }
        __syncthreads();
    }

    int r0 = lane >> 2, c0 = (lane & 3) * 2;
#pragma unroll
    for (int mt = 0; mt < 2; mt++)
#pragma unroll
        for (int nt = 0; nt < 8; nt++) {
            int m = blockIdx.y * 128 + wm * 32 + mt * 16 + r0;
            int n = blockIdx.x * 128 + wn * 64 + nt * 8 + c0;
            float2 v0 = make_float2(acc[mt][nt][0], acc[mt][nt][1]);
            float2 v1 = make_float2(acc[mt][nt][2], acc[mt][nt][3]);
            if (EPI) {
                float b0 = bias[n], b1 = bias[n + 1];
                v0.x = tanhf(v0.x + b0); v0.y = tanhf(v0.y + b1);
                v1.x = tanhf(v1.x + b0); v1.y = tanhf(v1.y + b1);
            }
            *(float2*)(C + (size_t)m * N + n) = v0;
            *(float2*)(C + (size_t)(m + 8) * N + n) = v1;
        }
}

// ---------------- LN over vocab table + init ----------------
__global__ void ln_k(const float* __restrict__ gA, const float* __restrict__ beA,
                     const float* __restrict__ bA, const float* __restrict__ gB,
                     const float* __restrict__ beB, const float* __restrict__ bB)
{
    int row = blockIdx.x, tid = threadIdx.x;
    if (row < 512) {
        ((float*)g_hbf)[row * 128 + tid] = 0.f;
    } else if (row == 512) {
        if (tid < 4) { g_ctrS[tid] = 0u; g_ctrH[tid] = 0u; }
    }
    int dir = row >= NV * 3;
    int rem = dir ? row - NV * 3 : row;
    int tok = rem / 3, gate = rem - tok * 3;
    float* p = (dir ? g_Wp1 : g_Wp0) + (size_t)tok * NH3 + gate * NH;
    const float* gg = (dir ? gB : gA) + gate * NH;
    const float* be = (dir ? beB : beA) + gate * NH;
    const float* bi = (dir ? bB : bA) + gate * NH;
    float4 v = ((float4*)p)[tid];
    if (tok == 0) { v.x = 0.f; v.y = 0.f; v.z = 0.f; v.w = 0.f; }
    float sum = v.x + v.y + v.z + v.w;
    float sq = v.x * v.x + v.y * v.y + v.z * v.z + v.w * v.w;
#pragma unroll
    for (int o = 16; o; o >>= 1) {
        sum += __shfl_xor_sync(0xffffffffu, sum, o);
        sq  += __shfl_xor_sync(0xffffffffu, sq, o);
    }
    __shared__ float ss[4], sc[4];
    int w = tid >> 5;
    if ((tid & 31) == 0) { ss[w] = sum; sc[w] = sq; }
    __syncthreads();
    sum = ss[0] + ss[1] + ss[2] + ss[3];
    sq  = sc[0] + sc[1] + sc[2] + sc[3];
    float mu = sum * (1.f / NH);
    float rs = rsqrtf(sq * (1.f / NH) - mu * mu + 1e-5f);
    int j = tid * 4;
    v.x = (v.x - mu) * rs * gg[j]     + be[j]     + bi[j];
    v.y = (v.y - mu) * rs * gg[j + 1] + be[j + 1] + bi[j + 1];
    v.z = (v.z - mu) * rs * gg[j + 2] + be[j + 2] + bi[j + 2];
    v.w = (v.w - mu) * rs * gg[j + 3] + be[j + 3] + bi[j + 3];
    ((float4*)p)[tid] = v;
}

// ----------------------------------------------------------------------------
// Persistent recurrence (Round-14 structure): counter barriers, register h,
// producer-side bf16 publish, private stat slots. New: LN stats fused into
// the combine pass via width-16 shfl butterflies; step-invariant combine
// indices precomputed (one less __syncthreads per step).
// ----------------------------------------------------------------------------
__global__ void __launch_bounds__(REC_THREADS, 1) gru_rec(
    const int* __restrict__ src,
    const float* __restrict__ Whh_f, const float* __restrict__ Whh_b,
    const float* __restrict__ ghh_f, const float* __restrict__ behh_f,
    const float* __restrict__ bhh_f, const float* __restrict__ ghh_b,
    const float* __restrict__ behh_b, const float* __restrict__ bhh_b,
    float* __restrict__ dout)
{
    extern __shared__ __align__(16) char smraw[];
    uint32_t sb0 = smem_u32(smraw);
    uint32_t sb = (sb0 + 1023) & ~1023u;
    char* basep = smraw + (sb - sb0);
    float* Pbuf = (float*)(basep + OFF_P);
    float* hpsp = (float*)(basep + OFF_HPS);
    float* sstat = (float*)(basep + OFF_SST);

    int grp = blockIdx.x >> 5, cid = blockIdx.x & 31;
    int dir = grp >> 1, bh = grp & 1;
    int tid = threadIdx.x, lane = tid & 31, wid = tid >> 5;
    int jbase = cid * JS;

    const float* Whh  = dir ? Whh_b  : Whh_f;
    const float* ghh  = dir ? ghh_b  : ghh_f;
    const float* behh = dir ? behh_b : behh_f;
    const float* bhh  = dir ? bhh_b  : bhh_f;
    const float* Wp   = dir ? g_Wp1  : g_Wp0;
    const uint4* hbhi = (const uint4*)g_hbf[grp][0];
    const uint4* hblo = (const uint4*)g_hbf[grp][1];
    unsigned* ctrS = &g_ctrS[grp];
    unsigned* ctrH = &g_ctrH[grp];

    // one-time: W -> bf16 hi/lo swizzled tiles
    for (int idx = tid; idx < NROW * 128; idx += REC_THREADS) {
        int r = idx >> 7, k4 = idx & 127;
        int grow = (r >> 4) * NH + jbase + (r & 15);
        float4 v = *(const float4*)(Whh + (size_t)grow * NH + k4 * 4);
        uint2 hi, lo; bsplit(v, hi, lo);
        uint32_t off = tile_off(r, k4);
        *(uint2*)(basep + OFF_WHI + off) = hi;
        *(uint2*)(basep + OFF_WLO + off) = lo;
    }

    int kh = wid / 6;
    int sp = wid % 6;
    bool t3 = sp >= 4;
    int mrowbase = t3 ? 0 : (sp >> 1) * 32;
    int ntb = t3 ? (sp - 4) * 24 : (sp & 1) * 24;
    int prow = t3 ? 64 : (sp >> 1) * 32;
    int khb = kh * 256;
    int aRow0 = mrowbase + (lane & 7) + ((lane >> 3) & 1) * 8;
    int aKoff = (lane >> 4) * 8;
    uint32_t swzl = (uint32_t)((lane & 7) << 4);
    uint32_t aBase0 = sb + OFF_A + aRow0 * 1024;
    uint32_t wTile = sb + (t3 ? OFF_WLO : OFF_WHI);
    int bKoff = ((lane >> 3) & 1) * 8;
    uint32_t bBase[3];
#pragma unroll
    for (int nt = 0; nt < 3; nt++)
        bBase[nt] = wTile + (ntb + nt * 8 + (lane & 7)) * 1024;

    int pb = tid >> 4, jl = tid & 15;
    float cg[3], cbe[3], cbb[3];
#pragma unroll
    for (int g = 0; g < 3; g++) {
        int j = g * NH + jbase + jl;
        cg[g] = ghh[j]; cbe[g] = behh[j]; cbb[g] = bhh[j];
    }

    // step-invariant combine indices: e_i = tid + i*512 -> (b, r, gate, lead)
    int cbI[3], crI[3], cst[3];
#pragma unroll
    for (int i = 0; i < 3; i++) {
        int e = tid + i * REC_THREADS;
        cbI[i] = e / 48;
        crI[i] = e - cbI[i] * 48;
        cst[i] = cbI[i] * 6 + (crI[i] >> 4) * 2;
    }
    bool lead16 = (tid & 15) == 0;

    float xv[3];
    {
        int s0 = dir ? (NS - 1) : 0;
        int tok = __ldg(src + s0 * NB + bh * NGB + pb);
        const float* xrow = Wp + (size_t)tok * NH3;
#pragma unroll
        for (int g = 0; g < 3; g++) xv[g] = __ldg(xrow + g * NH + jbase + jl);
    }
    float hprev = 0.f;
    __syncthreads();

    for (int t = 0; t < NS; t++) {
        int s = dir ? (NS - 1 - t) : t;

        if (t > 0) bar_wait(ctrH, (unsigned)(NCG * t));

        // L2-prefetch x(t+1) rows
        if (t + 1 < NS && (jl & 7) == 0) {
            int sn = dir ? (NS - 2 - t) : (t + 1);
            int tokp = __ldg(src + sn * NB + bh * NGB + pb);
            const float* xrp = Wp + (size_t)tokp * NH3 + jbase + jl;
#pragma unroll
            for (int g = 0; g < 3; g++)
                asm volatile("prefetch.global.L2 [%0];" :: "l"(xrp + g * NH));
        }

        // stage bf16 planes -> A tile (pure swizzled copy, 16B units)
#pragma unroll
        for (int i = 0; i < 8; i++) {
            int idx = tid + i * REC_THREADS;       // 0..4095
            int row = idx >> 6, u = idx & 63;
            const uint4* srcp = (row < 32) ? hbhi : hblo;
            uint4 v = srcp[(row & 31) * 64 + u];
            *(uint4*)(basep + OFF_A + row * 1024 + ((u * 16) ^ ((row & 7) << 4))) = v;
        }
        __syncthreads();

        if (wid < 12) {
            float acc[2][3][4];
#pragma unroll
            for (int mt = 0; mt < 2; mt++)
#pragma unroll
                for (int nt = 0; nt < 3; nt++)
#pragma unroll
                    for (int q = 0; q < 4; q++) acc[mt][nt][q] = 0.f;
#pragma unroll 4
            for (int kc = 0; kc < 16; kc++) {
                int kb = khb + kc * 16;
                uint32_t a0[4], a1[4];
                uint32_t ad = aBase0 + ((uint32_t)((kb + aKoff) * 2) ^ swzl);
                ldsm4(a0, ad);
                ldsm4(a1, ad + 16 * 1024);
                uint32_t bf[3][2];
                uint32_t bko = (uint32_t)((kb + bKoff) * 2) ^ swzl;
#pragma unroll
                for (int nt = 0; nt < 3; nt++) ldsm2(bf[nt], bBase[nt] + bko);
#pragma unroll
                for (int nt = 0; nt < 3; nt++) {
                    mma16816(acc[0][nt], a0, bf[nt]);
                    mma16816(acc[1][nt], a1, bf[nt]);
                }
            }
            float* P = Pbuf + kh * (96 * 50);
            int r0 = lane >> 2, c0 = (lane & 3) * 2;
#pragma unroll
            for (int mt = 0; mt < 2; mt++)
#pragma unroll
                for (int nt = 0; nt < 3; nt++) {
                    float* rp = P + (prow + mt * 16 + r0) * 50 + ntb + nt * 8 + c0;
                    *(float2*)rp = make_float2(acc[mt][nt][0], acc[mt][nt][1]);
                    *(float2*)(rp + 8 * 50) = make_float2(acc[mt][nt][2], acc[mt][nt][3]);
                }
        }
        __syncthreads();

        // combine partials -> hp[32][48] with fused width-16 LN-stat reduction
#pragma unroll
        for (int i = 0; i < 3; i++) {
            const float* P0 = Pbuf + cbI[i] * 50 + crI[i];
            const float* P1 = P0 + 96 * 50;
            float v = P0[0] + P0[32 * 50] + P0[64 * 50]
                    + P1[0] + P1[32 * 50] + P1[64 * 50];
            hpsp[cbI[i] * 52 + crI[i]] = v;
            float sv = v, sq = v * v;
#pragma unroll
            for (int o = 1; o < 16; o <<= 1) {
                sv += __shfl_xor_sync(0xffffffffu, sv, o);
                sq += __shfl_xor_sync(0xffffffffu, sq, o);
            }
            if (lead16)
                *(float2*)&g_pst[grp][cid][cst[i]] = make_float2(sv, sq);
        }
        bar_arrive(ctrS);

        // x(t+1) loads (hit L2 thanks to the step-top prefetch)
        float xn[3];
        if (t + 1 < NS) {
            int sn = dir ? (NS - 2 - t) : (t + 1);
            int tok = __ldg(src + sn * NB + bh * NGB + pb);
            const float* xrow = Wp + (size_t)tok * NH3;
#pragma unroll
            for (int g = 0; g < 3; g++) xn[g] = __ldg(xrow + g * NH + jbase + jl);
        }

        bar_wait(ctrS, (unsigned)(NCG * (t + 1)));

        // reduce stats across CTAs (192 threads, MLP-32 loads) -> smem broadcast
        if (tid < 192) {
            float v = 0.f;
#pragma unroll 8
            for (int c = 0; c < NCG; c++) v += g_pst[grp][c][tid];
            sstat[tid] = v;
        }
        __syncthreads();

        float hnew;
        {
            const float* st = sstat + pb * 6;
            float mu0 = st[0] * (1.f / NH);
            float rs0 = rsqrtf(st[1] * (1.f / NH) - mu0 * mu0 + 1e-5f);
            float mu1 = st[2] * (1.f / NH);
            float rs1 = rsqrtf(st[3] * (1.f / NH) - mu1 * mu1 + 1e-5f);
            float mu2 = st[4] * (1.f / NH);
            float rs2 = rsqrtf(st[5] * (1.f / NH) - mu2 * mu2 + 1e-5f);
            float hr = (hpsp[pb * 52 + jl]      - mu0) * rs0 * cg[0] + cbe[0] + cbb[0];
            float hz = (hpsp[pb * 52 + 16 + jl] - mu1) * rs1 * cg[1] + cbe[1] + cbb[1];
            float hn = (hpsp[pb * 52 + 32 + jl] - mu2) * rs2 * cg[2] + cbe[2] + cbb[2];
            float r = 1.f / (1.f + __expf(-(xv[0] + hr)));
            float z = 1.f / (1.f + __expf(-(xv[1] + hz)));
            float n = tanhf(xv[2] + r * hn);
            hnew = (1.f - z) * n + z * hprev;
            hprev = hnew;
            __nv_bfloat16 hi = __float2bfloat16_rn(hnew);
            __nv_bfloat16 lo = __float2bfloat16_rn(hnew - __bfloat162float(hi));
            g_hbf[grp][0][pb * NH + jbase + jl] = hi;
            g_hbf[grp][1][pb * NH + jbase + jl] = lo;
        }
        bar_arrive(ctrH);

        {
            int j = jbase + jl;
            int bglob = bh * NGB + pb;
            g_gru[((size_t)s * NB + bglob) * (2 * NH) + dir * NH + j] = hnew;
            if (t == NS - 1)
                dout[(size_t)NS * NB * NH + (size_t)dir * NB * NH + bglob * NH + j] = hnew;
        }
        xv[0] = xn[0]; xv[1] = xn[1]; xv[2] = xn[2];
    }
}

// ---------------- launch ----------------
extern "C" void kernel_launch(void* const* d_in, const int* in_sizes, int n_in,
                              void* d_out, int out_size) {
    (void)in_sizes; (void)n_in; (void)out_size;
    const int*   src    = (const int*)  d_in[0];
    const float* emb    = (const float*)d_in[1];
    const float* W_ih_f = (const float*)d_in[2];
    const float* W_hh_f = (const float*)d_in[3];
    const float* b_ih_f = (const float*)d_in[4];
    const float* bhh_f  = (const float*)d_in[5];
    const float* gih_f  = (const float*)d_in[6];
    const float* beih_f = (const float*)d_in[7];
    const float* ghh_f  = (const float*)d_in[8];
    const float* behh_f = (const float*)d_in[9];
    const float* W_ih_b = (const float*)d_in[10];
    const float* W_hh_b = (const float*)d_in[11];
    const float* b_ih_b = (const float*)d_in[12];
    const float* bhh_b  = (const float*)d_in[13];
    const float* gih_b  = (const float*)d_in[14];
    const float* beih_b = (const float*)d_in[15];
    const float* ghh_b  = (const float*)d_in[16];
    const float* behh_b = (const float*)d_in[17];
    const float* W_out  = (const float*)d_in[18];
    const float* b_out  = (const float*)d_in[19];
    float* out = (float*)d_out;

    void *pWp0, *pWp1, *pGru;
    cudaGetSymbolAddress(&pWp0, g_Wp0);
    cudaGetSymbolAddress(&pWp1, g_Wp1);
    cudaGetSymbolAddress(&pGru, g_gru);
    cudaFuncSetAttribute(gru_rec, cudaFuncAttributeMaxDynamicSharedMemorySize,
                         REC_SMEM_BYTES);
    cudaFuncSetAttribute(hgemm_nt<0>, cudaFuncAttributeMaxDynamicSharedMemorySize,
                         HG_SMEM);
    cudaFuncSetAttribute(hgemm_nt<1>, cudaFuncAttributeMaxDynamicSharedMemorySize,
                         HG_SMEM);

    hgemm_nt<0><<<dim3(NH3 / 128, NV / 128), 256, HG_SMEM>>>(
        emb, W_ih_f, (float*)pWp0, NV, NH3, NE, nullptr);
    hgemm_nt<0><<<dim3(NH3 / 128, NV / 128), 256, HG_SMEM>>>(
        emb, W_ih_b, (float*)pWp1, NV, NH3, NE, nullptr);

    ln_k<<<2 * NV * 3, 128>>>(gih_f, beih_f, b_ih_f, gih_b, beih_b, b_ih_b);

    gru_rec<<<128, REC_THREADS, REC_SMEM_BYTES>>>(
        src, W_hh_f, W_hh_b, ghh_f, behh_f, bhh_f, ghh_b, behh_b, bhh_b, out);

    hgemm_nt<1><<<dim3(NH / 128, (NS * NB) / 128), 256, HG_SMEM>>>(
        (const float*)pGru, W_out, out, NS * NB, NH, 2 * NH, b_out);
}